// round 11
// baseline (speedup 1.0000x reference)
#include <cuda_runtime.h>
#include <cuda_bf16.h>
#include <math.h>

// Problem constants
#define B_  16
#define T_  12
#define N_  325
#define D_  64
#define L_  2
#define G_  192
#define BN  (B_ * N_)          // 5200

// d_out layout (floats): output, hidden, attn_input, attn_hidden
#define SZ_OUT ((size_t)B_ * T_ * N_ * D_)
#define SZ_HID ((size_t)B_ * L_ * N_ * D_)
#define SZ_A   ((size_t)B_ * T_ * L_ * N_ * N_)
#define OFF_OUT 0
#define OFF_HID (SZ_OUT)
#define OFF_AI  (SZ_OUT + SZ_HID)
#define OFF_AH  (SZ_OUT + SZ_HID + SZ_A)

// Scratch (stream order serializes producer/consumer kernels)
__device__ float g_X[BN * D_];
__device__ float g_Q[2][BN * D_];
__device__ float g_K[2][BN * D_];
__device__ float g_O[2][BN * G_];

typedef unsigned long long ull;

__device__ __forceinline__ void ffma2(ull& d, ull a, ull b) {
    asm volatile("fma.rn.f32x2 %0, %1, %2, %0;" : "+l"(d) : "l"(a), "l"(b));
}
__device__ __forceinline__ float f2sum(ull v) {
    float lo, hi;
    asm("mov.b64 {%0, %1}, %2;" : "=f"(lo), "=f"(hi) : "l"(v));
    return lo + hi;
}

// FMA-pipe exp (x <= 0 here), ~1e-7 rel err.
__device__ __forceinline__ float fexp(float x) {
    float t = fmaxf(x * 1.4426950408889634f, -126.0f);
    float fi = floorf(t);
    float f = t - fi;
    float p =             1.535336188319500e-4f;
    p = fmaf(p, f, 1.339887440266574e-3f);
    p = fmaf(p, f, 9.618437357674640e-3f);
    p = fmaf(p, f, 5.550332471162809e-2f);
    p = fmaf(p, f, 2.402264791363012e-1f);
    p = fmaf(p, f, 6.931472028550421e-1f);
    p = fmaf(p, f, 1.0f);
    return p * __int_as_float(((int)fi + 127) << 23);
}

// ---------------------------------------------------------------------------
__global__ void zero_hidden_kernel(float* __restrict__ outf) {
    size_t i = (size_t)blockIdx.x * blockDim.x + threadIdx.x;
    if (i < SZ_HID) outf[OFF_HID + i] = 0.0f;
}

// ---------------------------------------------------------------------------
// K1: attention per (tile, gat, batch). grid (9, 2, 16)=288, block 256,
// smem 106 KB -> 2 CTAs/SM, single wave.
// Warp w owns rows w+8m (m<5) in every phase (no cross-warp S/Qs deps).
// Double-buffered 64-key chunks (1 sync/chunk, LDG overlapped).
// ---------------------------------------------------------------------------
#define RT     40
#define NTILES 9
#define NPADS  384
#define QSTR   68
#define KSTR   66
#define CH_ONE (64 * KSTR)                  // 4224
#define SM_S   (RT * QSTR)                  // 2720
#define SM_CH  (SM_S + RT * NPADS)          // 18080
#define K1_SMEM_FLOATS (SM_CH + 2 * CH_ONE) // 26528 -> 106,112 B

__global__ __launch_bounds__(256, 2)
void attn_kernel(int t, int l, int from_x,
                 const float* __restrict__ x,
                 const float* __restrict__ Wv_i, const float* __restrict__ Wv_h,
                 const float* __restrict__ b_i,  const float* __restrict__ b_h,
                 float* __restrict__ outf) {
    extern __shared__ float sm[];
    float* Qs = sm;               // RT x QSTR  (Q, then PX)
    float* S  = sm + SM_S;        // RT x NPADS (scores/P, then Wt)
    float* CH = sm + SM_CH;       // 2 x (64 x KSTR) chunk buffers

    const int rt   = blockIdx.x;
    const int g    = blockIdx.y;
    const int b    = blockIdx.z;
    const int tid  = threadIdx.x;
    const int w    = tid >> 5;
    const int lane = tid & 31;
    const int r0   = rt * RT;

    const float* Qg = g_Q[g] + (size_t)b * N_ * D_;
    const float* Kg = g_K[g] + (size_t)b * N_ * D_;
    const float* xsrc = from_x ? x + (((size_t)b * T_ + t) * N_) * D_
                               : g_X + (size_t)b * N_ * D_;

    // ---- load Q tile ----
    for (int idx = tid; idx < RT * 64; idx += 256) {
        int r = idx >> 6, d = idx & 63;
        int qr = r0 + r;
        Qs[r * QSTR + d] = (qr < N_) ? Qg[(size_t)qr * D_ + d] : 0.0f;
    }

    float4 ld[4];

    // ---- Phase 1: S = Q K^T / 8 (double-buffered 64-key chunks) ----
    // preload chunk 0 (key-major: lanes span d -> coalesced LDG, cf STS)
#pragma unroll
    for (int i = 0; i < 4; i++) {
        int idx = tid + 256 * i;
        int key = idx >> 4, d4 = idx & 15;
        float4 v = make_float4(0.f, 0.f, 0.f, 0.f);
        if (key < N_) v = *(const float4*)(Kg + (size_t)key * D_ + 4 * d4);
        ld[i] = v;
    }
#pragma unroll
    for (int i = 0; i < 4; i++) {
        int idx = tid + 256 * i;
        int bs = (idx >> 4) * KSTR + 4 * (idx & 15);
        CH[bs] = ld[i].x; CH[bs + 1] = ld[i].y; CH[bs + 2] = ld[i].z; CH[bs + 3] = ld[i].w;
    }
    __syncthreads();

    for (int kc = 0; kc < 6; kc++) {
        float* cur = CH + (kc & 1) * CH_ONE;
        float* nxt = CH + ((kc + 1) & 1) * CH_ONE;
        if (kc < 5) {
            const int kb1 = (kc + 1) * 64;
#pragma unroll
            for (int i = 0; i < 4; i++) {
                int idx = tid + 256 * i;
                int key = idx >> 4, d4 = idx & 15;
                int gk = kb1 + key;
                float4 v = make_float4(0.f, 0.f, 0.f, 0.f);
                if (gk < N_) v = *(const float4*)(Kg + (size_t)gk * D_ + 4 * d4);
                ld[i] = v;
            }
        }

        ull acc[5][2] = {};
#pragma unroll
        for (int k = 0; k < 64; k += 4) {
            ulonglong2 q[5];
#pragma unroll
            for (int m = 0; m < 5; m++)
                q[m] = *(const ulonglong2*)&Qs[(w + 8 * m) * QSTR + k];
#pragma unroll
            for (int j = 0; j < 2; j++) {
                const int co = (lane + 32 * j) * KSTR;
                ull k0 = *(const ull*)&cur[co + k];
                ull k1 = *(const ull*)&cur[co + k + 2];
#pragma unroll
                for (int m = 0; m < 5; m++) {
                    ffma2(acc[m][j], q[m].x, k0);
                    ffma2(acc[m][j], q[m].y, k1);
                }
            }
        }
        const int kb = kc * 64;
#pragma unroll
        for (int j = 0; j < 2; j++) {
            int c = kb + lane + 32 * j;
#pragma unroll
            for (int m = 0; m < 5; m++)
                S[(w + 8 * m) * NPADS + c] = f2sum(acc[m][j]) * 0.125f;
        }
        if (kc < 5) {
#pragma unroll
            for (int i = 0; i < 4; i++) {
                int idx = tid + 256 * i;
                int bs = (idx >> 4) * KSTR + 4 * (idx & 15);
                nxt[bs] = ld[i].x; nxt[bs + 1] = ld[i].y;
                nxt[bs + 2] = ld[i].z; nxt[bs + 3] = ld[i].w;
            }
            __syncthreads();
        }
    }
    __syncwarp();

    // ---- Softmax (rows w+8i -- same warp that wrote them) + attn write ----
    const size_t attn_base = (g == 0 ? OFF_AI : OFF_AH);
    for (int rr = w; rr < RT; rr += 8) {
        int qr = r0 + rr;
        if (qr < N_) {
            float mx = -1e30f;
            for (int i = lane; i < N_; i += 32) mx = fmaxf(mx, S[rr * NPADS + i]);
#pragma unroll
            for (int o = 16; o; o >>= 1) mx = fmaxf(mx, __shfl_xor_sync(0xffffffffu, mx, o));
            float s = 0.0f;
            for (int i = lane; i < NPADS; i += 32) {
                if (i < N_) {
                    float e = fexp(S[rr * NPADS + i] - mx);
                    S[rr * NPADS + i] = e;
                    s += e;
                } else S[rr * NPADS + i] = 0.0f;
            }
#pragma unroll
            for (int o = 16; o; o >>= 1) s += __shfl_xor_sync(0xffffffffu, s, o);
            float inv = 1.0f / s;
            float* arow = outf + attn_base +
                ((((size_t)b * T_ + t) * L_ + l) * N_ + qr) * (size_t)N_;
            for (int i = lane; i < N_; i += 32) {
                float p = S[rr * NPADS + i] * inv;
                S[rr * NPADS + i] = p;
                arow[i] = p;
            }
        } else {
            for (int i = lane; i < NPADS; i += 32) S[rr * NPADS + i] = 0.0f;
        }
    }

    // ---- Phase 2: PX = P @ x, x stored TRANSPOSED (CHt[c][key]) ----
    // preload chunk 0 (d-major: lanes span key -> conflict-free STS)
#pragma unroll
    for (int i = 0; i < 4; i++) {
        int idx = tid + 256 * i;
        int d4 = idx >> 6, key = idx & 63;
        float4 v = make_float4(0.f, 0.f, 0.f, 0.f);
        if (key < N_) v = *(const float4*)(xsrc + (size_t)key * D_ + 4 * d4);
        ld[i] = v;
    }
    __syncthreads();   // (also orders softmax S writes for all warps)
#pragma unroll
    for (int i = 0; i < 4; i++) {
        int idx = tid + 256 * i;
        int d4 = idx >> 6, key = idx & 63;
        CH[(4 * d4)     * KSTR + key] = ld[i].x;
        CH[(4 * d4 + 1) * KSTR + key] = ld[i].y;
        CH[(4 * d4 + 2) * KSTR + key] = ld[i].z;
        CH[(4 * d4 + 3) * KSTR + key] = ld[i].w;
    }
    __syncthreads();

    ull acc2[5][2] = {};
    for (int kc = 0; kc < 6; kc++) {
        float* cur = CH + (kc & 1) * CH_ONE;
        float* nxt = CH + ((kc + 1) & 1) * CH_ONE;
        if (kc < 5) {
            const int kb1 = (kc + 1) * 64;
#pragma unroll
            for (int i = 0; i < 4; i++) {
                int idx = tid + 256 * i;
                int d4 = idx >> 6, key = idx & 63;
                int gk = kb1 + key;
                float4 v = make_float4(0.f, 0.f, 0.f, 0.f);
                if (gk < N_) v = *(const float4*)(xsrc + (size_t)gk * D_ + 4 * d4);
                ld[i] = v;
            }
        }
        const int kb = kc * 64;
#pragma unroll
        for (int kk = 0; kk < 64; kk += 4) {
            ulonglong2 p[5];
#pragma unroll
            for (int m = 0; m < 5; m++)
                p[m] = *(const ulonglong2*)&S[(w + 8 * m) * NPADS + kb + kk];
#pragma unroll
            for (int j = 0; j < 2; j++) {
                const int co = (lane + 32 * j) * KSTR;
                ull x0 = *(const ull*)&cur[co + kk];
                ull x1 = *(const ull*)&cur[co + kk + 2];
#pragma unroll
                for (int m = 0; m < 5; m++) {
                    ffma2(acc2[m][j], p[m].x, x0);
                    ffma2(acc2[m][j], p[m].y, x1);
                }
            }
        }
        if (kc < 5) {
#pragma unroll
            for (int i = 0; i < 4; i++) {
                int idx = tid + 256 * i;
                int d4 = idx >> 6, key = idx & 63;
                nxt[(4 * d4)     * KSTR + key] = ld[i].x;
                nxt[(4 * d4 + 1) * KSTR + key] = ld[i].y;
                nxt[(4 * d4 + 2) * KSTR + key] = ld[i].z;
                nxt[(4 * d4 + 3) * KSTR + key] = ld[i].w;
            }
            __syncthreads();
        }
    }
    // PX -> Qs (own rows)
#pragma unroll
    for (int m = 0; m < 5; m++)
#pragma unroll
        for (int j = 0; j < 2; j++)
            Qs[(w + 8 * m) * QSTR + lane + 32 * j] = f2sum(acc2[m][j]);
    __syncthreads();   // all P reads done before Wt overwrites S

    // ---- Phase 3: O = PX @ Wv + bias -> g_O ----
    const float* W    = (g ? Wv_h : Wv_i) + (size_t)l * D_ * G_;
    const float* bias = (g ? b_h : b_i) + (size_t)l * G_;
    float* Wt = S;                     // 192 x KSTR = 12672 <= 15360
    for (int idx = tid; idx < 64 * G_; idx += 256) {
        int d = idx / G_, c = idx % G_;
        Wt[c * KSTR + d] = W[d * G_ + c];
    }
    __syncthreads();

    float* Og = g_O[g] + (size_t)b * N_ * G_;
#pragma unroll
    for (int jg = 0; jg < 3; jg++) {
        ull acc3[5][2] = {};
#pragma unroll
        for (int d = 0; d < 64; d += 4) {
            ulonglong2 px[5];
#pragma unroll
            for (int m = 0; m < 5; m++)
                px[m] = *(const ulonglong2*)&Qs[(w + 8 * m) * QSTR + d];
#pragma unroll
            for (int j = 0; j < 2; j++) {
                const int c = jg * 64 + lane + 32 * j;
                ull w0 = *(const ull*)&Wt[c * KSTR + d];
                ull w1 = *(const ull*)&Wt[c * KSTR + d + 2];
#pragma unroll
                for (int m = 0; m < 5; m++) {
                    ffma2(acc3[m][j], px[m].x, w0);
                    ffma2(acc3[m][j], px[m].y, w1);
                }
            }
        }
#pragma unroll
        for (int m = 0; m < 5; m++) {
            int qr = r0 + w + 8 * m;
            if (qr < N_) {
#pragma unroll
                for (int j = 0; j < 2; j++) {
                    int col = jg * 64 + lane + 32 * j;
                    Og[(size_t)qr * G_ + col] = f2sum(acc3[m][j]) + __ldg(&bias[col]);
                }
            }
        }
    }
}

// ---------------------------------------------------------------------------
// K2: GRU gate + LayerNorm + next-stage Q/K. grid (21, 16)=336, block 256.
// 16 rows/CTA. QK reads weights directly from global (coalesced, L2-hot).
// ---------------------------------------------------------------------------
#define RT2 16

__global__ __launch_bounds__(256)
void gate_qk_kernel(int t, int l, int do_gate, int do_qk, int l_next, int tx,
                    const float* __restrict__ x,
                    const float* __restrict__ Wq_i, const float* __restrict__ Wk_i,
                    const float* __restrict__ Wq_h, const float* __restrict__ Wk_h,
                    const float* __restrict__ ln_g, const float* __restrict__ ln_b,
                    float* __restrict__ outf) {
    __shared__ float Ys[RT2 * QSTR];

    const int rt   = blockIdx.x;
    const int b    = blockIdx.y;
    const int tid  = threadIdx.x;
    const int w    = tid >> 5;
    const int lane = tid & 31;
    const int r0   = rt * RT2;

    if (do_gate) {
#pragma unroll
        for (int rx = 0; rx < 2; rx++) {
            int rr = 2 * w + rx;
            int qr = r0 + rr;
            float o0 = 0.0f, o1 = 0.0f;
            float* hid = 0;
            if (qr < N_) {
                const float* oi = g_O[0] + ((size_t)b * N_ + qr) * G_;
                const float* oh = g_O[1] + ((size_t)b * N_ + qr) * G_;
                hid = outf + OFF_HID + (((size_t)b * L_ + l) * N_ + qr) * D_;
                int d0 = lane, d1 = lane + 32;
                float h0 = hid[d0], h1 = hid[d1];
                float rg0 = 1.0f / (1.0f + expf(-(oi[d0]       + oh[d0])));
                float ig0 = 1.0f / (1.0f + expf(-(oi[64 + d0]  + oh[64 + d0])));
                float ng0 = tanhf(oi[128 + d0] + rg0 * oh[128 + d0]);
                o0 = ng0 + ig0 * (h0 - ng0);
                float rg1 = 1.0f / (1.0f + expf(-(oi[d1]       + oh[d1])));
                float ig1 = 1.0f / (1.0f + expf(-(oi[64 + d1]  + oh[64 + d1])));
                float ng1 = tanhf(oi[128 + d1] + rg1 * oh[128 + d1]);
                o1 = ng1 + ig1 * (h1 - ng1);
            }
            float s = o0 + o1, q = o0 * o0 + o1 * o1;
#pragma unroll
            for (int off = 16; off; off >>= 1) {
                s += __shfl_xor_sync(0xffffffffu, s, off);
                q += __shfl_xor_sync(0xffffffffu, q, off);
            }
            if (qr < N_) {
                float mu  = s * (1.0f / 64.0f);
                float var = q * (1.0f / 64.0f) - mu * mu;
                float rs  = rsqrtf(var + 1e-5f);
                int d0 = lane, d1 = lane + 32;
                float y0 = (o0 - mu) * rs * __ldg(&ln_g[l * D_ + d0]) + __ldg(&ln_b[l * D_ + d0]);
                float y1 = (o1 - mu) * rs * __ldg(&ln_g[l * D_ + d1]) + __ldg(&ln_b[l * D_ + d1]);
                hid[d0] = y0; hid[d1] = y1;
                float* gx = g_X + ((size_t)b * N_ + qr) * D_;
                gx[d0] = y0; gx[d1] = y1;
                if (l == L_ - 1) {
                    float* po = outf + OFF_OUT + (((size_t)b * T_ + t) * N_ + qr) * D_;
                    po[d0] = y0; po[d1] = y1;
                }
                Ys[rr * QSTR + d0] = y0; Ys[rr * QSTR + d1] = y1;
            } else {
                Ys[rr * QSTR + lane] = 0.0f; Ys[rr * QSTR + lane + 32] = 0.0f;
            }
        }
    }

    if (!do_qk) return;
    __syncthreads();

    if (l_next == 0) {
        const float* xn = x + (((size_t)b * T_ + tx) * N_) * D_;
        for (int idx = tid; idx < RT2 * 64; idx += 256) {
            int r = idx >> 6, d = idx & 63;
            int qr = r0 + r;
            Ys[r * QSTR + d] = (qr < N_) ? xn[(size_t)qr * D_ + d] : 0.0f;
        }
        __syncthreads();
    }

    // warp w: mat = w&3 (0:Qi 1:Ki 2:Qh 3:Kh), rows (w>>2)*8 .. +8
    const int mat = w & 3;
    const int rh  = (w >> 2) * 8;
    const float* Wm =
        ((mat == 0) ? Wq_i : (mat == 1) ? Wk_i : (mat == 2) ? Wq_h : Wk_h)
        + (size_t)l_next * D_ * D_;
    float acc[8][2] = {};
#pragma unroll 8
    for (int k = 0; k < 64; k++) {
        float wv0 = __ldg(&Wm[k * 64 + lane]);
        float wv1 = __ldg(&Wm[k * 64 + lane + 32]);
#pragma unroll
        for (int r = 0; r < 8; r++) {
            float yv = Ys[(rh + r) * QSTR + k];
            acc[r][0] = fmaf(yv, wv0, acc[r][0]);
            acc[r][1] = fmaf(yv, wv1, acc[r][1]);
        }
    }
    float* Dd = ((mat & 1) ? g_K[mat >> 1] : g_Q[mat >> 1]) + (size_t)b * N_ * D_;
#pragma unroll
    for (int r = 0; r < 8; r++) {
        int qr = r0 + rh + r;
        if (qr < N_) {
            Dd[(size_t)qr * D_ + lane]      = acc[r][0];
            Dd[(size_t)qr * D_ + lane + 32] = acc[r][1];
        }
    }
}

// ---------------------------------------------------------------------------
extern "C" void kernel_launch(void* const* d_in, const int* in_sizes, int n_in,
                              void* d_out, int out_size) {
    const float* x    = (const float*)d_in[0];
    const float* Wq_i = (const float*)d_in[1];
    const float* Wk_i = (const float*)d_in[2];
    const float* Wv_i = (const float*)d_in[3];
    const float* b_i  = (const float*)d_in[4];
    const float* Wq_h = (const float*)d_in[5];
    const float* Wk_h = (const float*)d_in[6];
    const float* Wv_h = (const float*)d_in[7];
    const float* b_h  = (const float*)d_in[8];
    const float* ln_g = (const float*)d_in[9];
    const float* ln_b = (const float*)d_in[10];
    float* outf = (float*)d_out;

    const int k1_smem = K1_SMEM_FLOATS * (int)sizeof(float);  // 106,112 B
    cudaFuncSetAttribute(attn_kernel, cudaFuncAttributeMaxDynamicSharedMemorySize, k1_smem);

    zero_hidden_kernel<<<(int)((SZ_HID + 255) / 256), 256>>>(outf);

    dim3 k1_grid(NTILES, 2, 16);
    dim3 k2_grid(21, 16);

    // prologue: Q/K for stage (0,0) from x[:,0]
    gate_qk_kernel<<<k2_grid, 256>>>(0, 0, /*do_gate*/0, /*do_qk*/1,
                                     /*l_next*/0, /*tx*/0, x,
                                     Wq_i, Wk_i, Wq_h, Wk_h, ln_g, ln_b, outf);

    for (int s = 0; s < T_ * L_; s++) {
        int t = s >> 1, l = s & 1;
        attn_kernel<<<k1_grid, 256, k1_smem>>>(t, l, (l == 0) ? 1 : 0, x,
                                               Wv_i, Wv_h, b_i, b_h, outf);
        gate_qk_kernel<<<k2_grid, 256>>>(t, l, 1, (s < T_ * L_ - 1) ? 1 : 0,
                                         l ^ 1, t + 1, x,
                                         Wq_i, Wk_i, Wq_h, Wk_h, ln_g, ln_b, outf);
    }
}